// round 6
// baseline (speedup 1.0000x reference)
#include <cuda_runtime.h>
#include <cuda_bf16.h>

// Problem shape (fixed by dataset)
#define NMAX 50000
#define EMAX 600000
#define DIM  128
#define GR   16      // rows per block in QKV GEMM

// ---------------- device scratch (static allocation only) ----------------
__device__ float g_Q[NMAX * DIM];
__device__ float g_K[NMAX * DIM];
__device__ float g_V[NMAX * DIM];
__device__ float g_expAtt[EMAX * 4];
__device__ int   g_deg[NMAX];
__device__ int   g_rowptr[NMAX + 1];
__device__ int   g_cursor[NMAX];
__device__ int   g_eperm[EMAX];

// ---------------- kernel 0: zero degree array ----------------
__global__ void zero_deg_kernel(int n) {
    int i = blockIdx.x * blockDim.x + threadIdx.x;
    if (i < n) g_deg[i] = 0;
}

// ---------------- kernel 1: fused Q/K/V projection ----------------
// Q[r][j] = sum_k emb[r][k] * qW[k][j]  (same for K, V).
// 128 threads = one output column j each; GR=16 rows per block.
// Each thread keeps 16 accumulators per matrix (48 total), reads the
// embedding tile from shared memory (broadcast: all threads read the same
// et[k][r] in a given inner step).
__global__ void __launch_bounds__(128) qkv_kernel(
    const float* __restrict__ emb,
    const float* __restrict__ wq,
    const float* __restrict__ wk,
    const float* __restrict__ wv,
    int n)
{
    __shared__ float et[GR][DIM];                 // row-major tile
    const int j  = threadIdx.x;                   // output column 0..127
    const int r0 = blockIdx.x * GR;

    #pragma unroll
    for (int r = 0; r < GR; r++) {
        int row = r0 + r;
        et[r][j] = (row < n) ? emb[row * DIM + j] : 0.f;
    }
    __syncthreads();

    float aq[GR], ak[GR], av[GR];
    #pragma unroll
    for (int r = 0; r < GR; r++) { aq[r] = 0.f; ak[r] = 0.f; av[r] = 0.f; }

    #pragma unroll 4
    for (int k = 0; k < DIM; k++) {
        float wqv = __ldg(&wq[k * DIM + j]);
        float wkv = __ldg(&wk[k * DIM + j]);
        float wvv = __ldg(&wv[k * DIM + j]);
        #pragma unroll
        for (int r = 0; r < GR; r++) {
            float e = et[r][k];                   // broadcast across the block
            aq[r] = fmaf(e, wqv, aq[r]);
            ak[r] = fmaf(e, wkv, ak[r]);
            av[r] = fmaf(e, wvv, av[r]);
        }
    }

    #pragma unroll
    for (int r = 0; r < GR; r++) {
        int row = r0 + r;
        if (row < n) {
            g_Q[row * DIM + j] = aq[r];
            g_K[row * DIM + j] = ak[r];
            g_V[row * DIM + j] = av[r];
        }
    }
}

// ---------------- kernel 2: degree histogram ----------------
__global__ void hist_kernel(const int* __restrict__ rows, int E) {
    int i = blockIdx.x * blockDim.x + threadIdx.x;
    if (i < E) atomicAdd(&g_deg[rows[i]], 1);
}

// ---------------- kernel 3: exclusive scan (single block, 8 elems/thread) ----------------
__global__ void scan_kernel(int n) {
    __shared__ int ss[1024];
    __shared__ int sbase;
    const int tid = threadIdx.x;
    if (tid == 0) sbase = 0;
    __syncthreads();

    const int nch = (n + 8191) / 8192;
    for (int ch = 0; ch < nch; ch++) {
        int base = ch * 8192 + tid * 8;
        int v[8];
        int tot = 0;
        #pragma unroll
        for (int i = 0; i < 8; i++) {
            int idx = base + i;
            int d = (idx < n) ? g_deg[idx] : 0;
            v[i] = tot;      // exclusive within thread
            tot += d;
        }
        ss[tid] = tot;
        __syncthreads();
        // inclusive Hillis-Steele over 1024 thread totals
        for (int off = 1; off < 1024; off <<= 1) {
            int t = (tid >= off) ? ss[tid - off] : 0;
            __syncthreads();
            ss[tid] += t;
            __syncthreads();
        }
        int prev = (tid > 0) ? ss[tid - 1] : 0;
        int b = sbase;
        #pragma unroll
        for (int i = 0; i < 8; i++) {
            int idx = base + i;
            if (idx < n) {
                int val = b + prev + v[i];
                g_rowptr[idx] = val;
                g_cursor[idx] = val;
            }
        }
        int total = ss[1023];
        __syncthreads();
        if (tid == 0) sbase = b + total;
        __syncthreads();
    }
    if (tid == 0) g_rowptr[n] = sbase;
}

// ---------------- kernel 4: scatter edge ids into CSR ----------------
__global__ void scatter_kernel(const int* __restrict__ rows, int E) {
    int i = blockIdx.x * blockDim.x + threadIdx.x;
    if (i < E) {
        int pos = atomicAdd(&g_cursor[rows[i]], 1);
        g_eperm[pos] = i;
    }
}

// ---------------- kernel 5: fused segment-softmax attention ----------------
// One warp per destination node. Lane l holds dims [4l, 4l+4); head = l>>3.
__global__ void __launch_bounds__(256) attn_kernel(
    const int* __restrict__ cols, float* __restrict__ out, int n)
{
    int gw   = (blockIdx.x * blockDim.x + threadIdx.x) >> 5;
    int lane = threadIdx.x & 31;
    if (gw >= n) return;

    const float4* Q4 = (const float4*)g_Q;
    const float4* K4 = (const float4*)g_K;
    const float4* V4 = (const float4*)g_V;

    float4 qv = Q4[gw * 32 + lane];
    int beg = g_rowptr[gw];
    int end = g_rowptr[gw + 1];

    // pass A: logits -> exp -> stash, accumulate per-head norm
    float nsum = 0.f;
    for (int idx = beg; idx < end; idx++) {
        int e = g_eperm[idx];
        int c = __ldg(&cols[e]);
        float4 kv = K4[c * 32 + lane];
        float p = fmaf(qv.x, kv.x, fmaf(qv.y, kv.y, fmaf(qv.z, kv.z, qv.w * kv.w)));
        p += __shfl_xor_sync(0xffffffffu, p, 1);
        p += __shfl_xor_sync(0xffffffffu, p, 2);
        p += __shfl_xor_sync(0xffffffffu, p, 4);   // full head dot in all 8 lanes of group
        float a  = fminf(fmaxf(p, -10.f), 10.f);
        float ea = __expf(a);
        if ((lane & 7) == 0) g_expAtt[e * 4 + (lane >> 3)] = ea;
        nsum += ea;
    }
    __syncwarp();

    // pass B: normalize and accumulate V
    float inv = 1.f / (nsum + 1e-8f);
    int h = lane >> 3;
    float4 acc = make_float4(0.f, 0.f, 0.f, 0.f);
    for (int idx = beg; idx < end; idx++) {
        int e = g_eperm[idx];
        int c = __ldg(&cols[e]);
        float w = g_expAtt[e * 4 + h] * inv;
        float4 vv = V4[c * 32 + lane];
        acc.x = fmaf(w, vv.x, acc.x);
        acc.y = fmaf(w, vv.y, acc.y);
        acc.z = fmaf(w, vv.z, acc.z);
        acc.w = fmaf(w, vv.w, acc.w);
    }
    ((float4*)out)[gw * 32 + lane] = acc;
}

// ---------------- launch ----------------
extern "C" void kernel_launch(void* const* d_in, const int* in_sizes, int n_in,
                              void* d_out, int out_size) {
    const float* emb  = (const float*)d_in[0];
    const float* qW   = (const float*)d_in[1];
    const float* kW   = (const float*)d_in[2];
    const float* vW   = (const float*)d_in[3];
    const int*   rows = (const int*)d_in[4];
    const int*   cols = (const int*)d_in[5];
    float*       out  = (float*)d_out;

    const int N = in_sizes[0] / DIM;   // 50000
    const int E = in_sizes[4];         // 600000

    zero_deg_kernel<<<(N + 255) / 256, 256>>>(N);
    qkv_kernel<<<(N + GR - 1) / GR, 128>>>(emb, qW, kW, vW, N);
    hist_kernel<<<(E + 255) / 256, 256>>>(rows, E);
    scan_kernel<<<1, 1024>>>(N);
    scatter_kernel<<<(E + 255) / 256, 256>>>(rows, E);
    attn_kernel<<<(N + 7) / 8, 256>>>(cols, out, N);
}

// round 7
// speedup vs baseline: 1.1480x; 1.1480x over previous
#include <cuda_runtime.h>
#include <cuda_bf16.h>

// Problem shape (fixed by dataset)
#define NMAX 50000
#define EMAX 600000
#define DIM  128
#define GR   16      // rows per block in QKV GEMM

// ---------------- device scratch (static allocation only) ----------------
__device__ float g_Q[NMAX * DIM];
__device__ float g_K[NMAX * DIM];
__device__ float g_V[NMAX * DIM];
__device__ float g_expAtt[EMAX * 4];
__device__ int   g_deg[NMAX];
__device__ int   g_rowptr[NMAX + 1];
__device__ int   g_cursor[NMAX];
__device__ int   g_eperm[EMAX];

// ---------------- packed f32x2 helpers ----------------
__device__ __forceinline__ void ffma2(unsigned long long& acc,
                                      unsigned long long a,
                                      unsigned long long b) {
    asm("fma.rn.f32x2 %0, %1, %2, %0;" : "+l"(acc) : "l"(a), "l"(b));
}
__device__ __forceinline__ unsigned long long bcast2(float x) {
    unsigned long long r;
    unsigned u = __float_as_uint(x);
    asm("mov.b64 %0, {%1, %1};" : "=l"(r) : "r"(u));
    return r;
}
__device__ __forceinline__ void unpack2(unsigned long long v, float& lo, float& hi) {
    unsigned a, b;
    asm("mov.b64 {%0, %1}, %2;" : "=r"(a), "=r"(b) : "l"(v));
    lo = __uint_as_float(a);
    hi = __uint_as_float(b);
}

// ---------------- kernel 0: zero degree array ----------------
__global__ void zero_deg_kernel(int n) {
    int i = blockIdx.x * blockDim.x + threadIdx.x;
    if (i < n) g_deg[i] = 0;
}

// ---------------- kernel 1: fused Q/K/V projection (packed f32x2) ----------------
// Q[r][j] = sum_k emb[r][k] * qW[k][j]  (same for K, V).
// 128 threads = one output column j each; GR=16 rows per block.
// Shared tile stored k-major (et[k][r]) so adjacent rows pack into f32x2;
// fma.rn.f32x2 halves the fp32 issue count (FFMA2 is PTX-only, ptxas never fuses).
__global__ void __launch_bounds__(128) qkv_kernel(
    const float* __restrict__ emb,
    const float* __restrict__ wq,
    const float* __restrict__ wk,
    const float* __restrict__ wv,
    int n)
{
    __shared__ __align__(16) float et[DIM][20];   // 20 floats = 80B stride (16B aligned, bank spread)
    const int j  = threadIdx.x;                   // output column 0..127
    const int r0 = blockIdx.x * GR;

    #pragma unroll
    for (int r = 0; r < GR; r++) {
        int row = r0 + r;
        et[j][r] = (row < n) ? emb[row * DIM + j] : 0.f;
    }
    __syncthreads();

    // 8 packed accumulators per matrix: pair i = rows (2i, 2i+1)
    unsigned long long aq[8], ak[8], av[8];
    #pragma unroll
    for (int i = 0; i < 8; i++) { aq[i] = 0ull; ak[i] = 0ull; av[i] = 0ull; }

    #pragma unroll 4
    for (int k = 0; k < DIM; k++) {
        unsigned long long q2 = bcast2(__ldg(&wq[k * DIM + j]));
        unsigned long long k2 = bcast2(__ldg(&wk[k * DIM + j]));
        unsigned long long v2 = bcast2(__ldg(&wv[k * DIM + j]));
        const ulonglong2* ep = (const ulonglong2*)(&et[k][0]);  // rows packed pairwise
        #pragma unroll
        for (int p = 0; p < 4; p++) {
            ulonglong2 e2 = ep[p];
            ffma2(aq[2 * p],     e2.x, q2);
            ffma2(aq[2 * p + 1], e2.y, q2);
            ffma2(ak[2 * p],     e2.x, k2);
            ffma2(ak[2 * p + 1], e2.y, k2);
            ffma2(av[2 * p],     e2.x, v2);
            ffma2(av[2 * p + 1], e2.y, v2);
        }
    }

    #pragma unroll
    for (int i = 0; i < 8; i++) {
        float qlo, qhi, klo, khi, vlo, vhi;
        unpack2(aq[i], qlo, qhi);
        unpack2(ak[i], klo, khi);
        unpack2(av[i], vlo, vhi);
        int row = r0 + 2 * i;
        if (row < n) {
            g_Q[row * DIM + j] = qlo;
            g_K[row * DIM + j] = klo;
            g_V[row * DIM + j] = vlo;
        }
        if (row + 1 < n) {
            g_Q[(row + 1) * DIM + j] = qhi;
            g_K[(row + 1) * DIM + j] = khi;
            g_V[(row + 1) * DIM + j] = vhi;
        }
    }
}

// ---------------- kernel 2: degree histogram ----------------
__global__ void hist_kernel(const int* __restrict__ rows, int E) {
    int i = blockIdx.x * blockDim.x + threadIdx.x;
    if (i < E) atomicAdd(&g_deg[rows[i]], 1);
}

// ---------------- kernel 3: exclusive scan (single block, warp-shuffle hierarchy) ----------------
// 1024 threads, 8 elems/thread, 8192-elem chunks. 3 barriers per chunk.
__global__ void __launch_bounds__(1024) scan_kernel(int n) {
    __shared__ int warp_off[32];   // exclusive offsets of each warp within chunk
    __shared__ int s_total;        // chunk total
    __shared__ int s_carry;        // running prefix across chunks
    const int tid  = threadIdx.x;
    const int lane = tid & 31;
    const int wid  = tid >> 5;
    if (tid == 0) s_carry = 0;
    __syncthreads();

    const int nch = (n + 8191) / 8192;
    for (int ch = 0; ch < nch; ch++) {
        int base = ch * 8192 + tid * 8;
        int v[8];
        int tot = 0;
        #pragma unroll
        for (int i = 0; i < 8; i++) {
            int idx = base + i;
            int d = (idx < n) ? g_deg[idx] : 0;
            v[i] = tot;            // exclusive within thread
            tot += d;
        }
        // warp-inclusive scan of thread totals
        int inc = tot;
        #pragma unroll
        for (int off = 1; off < 32; off <<= 1) {
            int t = __shfl_up_sync(0xffffffffu, inc, off);
            if (lane >= off) inc += t;
        }
        if (lane == 31) warp_off[wid] = inc;   // warp total (inclusive of whole warp)
        int texcl = inc - tot;                 // exclusive within warp
        __syncthreads();

        // warp 0 scans the 32 warp totals
        if (wid == 0) {
            int w  = warp_off[lane];
            int wi = w;
            #pragma unroll
            for (int off = 1; off < 32; off <<= 1) {
                int t = __shfl_up_sync(0xffffffffu, wi, off);
                if (lane >= off) wi += t;
            }
            warp_off[lane] = wi - w;           // exclusive warp offset
            if (lane == 31) s_total = wi;      // chunk total
        }
        __syncthreads();

        int b = s_carry + warp_off[wid] + texcl;
        #pragma unroll
        for (int i = 0; i < 8; i++) {
            int idx = base + i;
            if (idx < n) {
                int val = b + v[i];
                g_rowptr[idx] = val;
                g_cursor[idx] = val;
            }
        }
        __syncthreads();                       // all reads of s_carry/warp_off done
        if (tid == 0) s_carry += s_total;
        __syncthreads();                       // new s_carry visible; warp_off reusable
    }
    if (tid == 0) g_rowptr[n] = s_carry;
}

// ---------------- kernel 4: scatter edge ids into CSR ----------------
__global__ void scatter_kernel(const int* __restrict__ rows, int E) {
    int i = blockIdx.x * blockDim.x + threadIdx.x;
    if (i < E) {
        int pos = atomicAdd(&g_cursor[rows[i]], 1);
        g_eperm[pos] = i;
    }
}

// ---------------- kernel 5: fused segment-softmax attention ----------------
// One warp per destination node. Lane l holds dims [4l, 4l+4); head = l>>3.
__global__ void __launch_bounds__(256) attn_kernel(
    const int* __restrict__ cols, float* __restrict__ out, int n)
{
    int gw   = (blockIdx.x * blockDim.x + threadIdx.x) >> 5;
    int lane = threadIdx.x & 31;
    if (gw >= n) return;

    const float4* Q4 = (const float4*)g_Q;
    const float4* K4 = (const float4*)g_K;
    const float4* V4 = (const float4*)g_V;

    float4 qv = Q4[gw * 32 + lane];
    int beg = g_rowptr[gw];
    int end = g_rowptr[gw + 1];

    // pass A: logits -> exp -> stash, accumulate per-head norm
    float nsum = 0.f;
    for (int idx = beg; idx < end; idx++) {
        int e = g_eperm[idx];
        int c = __ldg(&cols[e]);
        float4 kv = K4[c * 32 + lane];
        float p = fmaf(qv.x, kv.x, fmaf(qv.y, kv.y, fmaf(qv.z, kv.z, qv.w * kv.w)));
        p += __shfl_xor_sync(0xffffffffu, p, 1);
        p += __shfl_xor_sync(0xffffffffu, p, 2);
        p += __shfl_xor_sync(0xffffffffu, p, 4);   // full head dot in all 8 lanes of group
        float a  = fminf(fmaxf(p, -10.f), 10.f);
        float ea = __expf(a);
        if ((lane & 7) == 0) g_expAtt[e * 4 + (lane >> 3)] = ea;
        nsum += ea;
    }
    __syncwarp();

    // pass B: normalize and accumulate V
    float inv = 1.f / (nsum + 1e-8f);
    int h = lane >> 3;
    float4 acc = make_float4(0.f, 0.f, 0.f, 0.f);
    for (int idx = beg; idx < end; idx++) {
        int e = g_eperm[idx];
        int c = __ldg(&cols[e]);
        float w = g_expAtt[e * 4 + h] * inv;
        float4 vv = V4[c * 32 + lane];
        acc.x = fmaf(w, vv.x, acc.x);
        acc.y = fmaf(w, vv.y, acc.y);
        acc.z = fmaf(w, vv.z, acc.z);
        acc.w = fmaf(w, vv.w, acc.w);
    }
    ((float4*)out)[gw * 32 + lane] = acc;
}

// ---------------- launch ----------------
extern "C" void kernel_launch(void* const* d_in, const int* in_sizes, int n_in,
                              void* d_out, int out_size) {
    const float* emb  = (const float*)d_in[0];
    const float* qW   = (const float*)d_in[1];
    const float* kW   = (const float*)d_in[2];
    const float* vW   = (const float*)d_in[3];
    const int*   rows = (const int*)d_in[4];
    const int*   cols = (const int*)d_in[5];
    float*       out  = (float*)d_out;

    const int N = in_sizes[0] / DIM;   // 50000
    const int E = in_sizes[4];         // 600000

    zero_deg_kernel<<<(N + 255) / 256, 256>>>(N);
    qkv_kernel<<<(N + GR - 1) / GR, 128>>>(emb, qW, kW, vW, N);
    hist_kernel<<<(E + 255) / 256, 256>>>(rows, E);
    scan_kernel<<<1, 1024>>>(N);
    scatter_kernel<<<(E + 255) / 256, 256>>>(rows, E);
    attn_kernel<<<(N + 7) / 8, 256>>>(cols, out, N);
}

// round 8
// speedup vs baseline: 1.4202x; 1.2371x over previous
#include <cuda_runtime.h>
#include <cuda_bf16.h>

// Problem shape (fixed by dataset)
#define NMAX 50000
#define EMAX 600000
#define DIM  128
#define GR   16        // rows per block in QKV GEMM
#define SCAN_TILE 2048 // elems per scan block (256 thr x 8)
#define SCAN_MAXB 64   // max scan blocks (50000/2048 -> 25)

// ---------------- device scratch (static allocation only) ----------------
__device__ float g_Q[NMAX * DIM];
__device__ float g_K[NMAX * DIM];
__device__ float g_V[NMAX * DIM];
__device__ float g_expAtt[EMAX * 4];
__device__ int   g_deg[NMAX + 8];      // padded so int4 loads never fault
__device__ int   g_rowptr[NMAX + 1];
__device__ int   g_cursor[NMAX];
__device__ int   g_eperm[EMAX];
__device__ int   g_bsum[SCAN_MAXB];
__device__ int   g_boff[SCAN_MAXB];

// ---------------- packed f32x2 helpers ----------------
__device__ __forceinline__ void ffma2(unsigned long long& acc,
                                      unsigned long long a,
                                      unsigned long long b) {
    asm("fma.rn.f32x2 %0, %1, %2, %0;" : "+l"(acc) : "l"(a), "l"(b));
}
__device__ __forceinline__ unsigned long long bcast2(float x) {
    unsigned long long r;
    unsigned u = __float_as_uint(x);
    asm("mov.b64 %0, {%1, %1};" : "=l"(r) : "r"(u));
    return r;
}
__device__ __forceinline__ void unpack2(unsigned long long v, float& lo, float& hi) {
    unsigned a, b;
    asm("mov.b64 {%0, %1}, %2;" : "=r"(a), "=r"(b) : "l"(v));
    lo = __uint_as_float(a);
    hi = __uint_as_float(b);
}

// ---------------- kernel 0: zero degree array (incl. pad) ----------------
__global__ void zero_deg_kernel(int n) {
    int i = blockIdx.x * blockDim.x + threadIdx.x;
    if (i < n + 8) g_deg[i] = 0;
}

// ---------------- kernel 1: fused Q/K/V projection (packed f32x2) ----------------
__global__ void __launch_bounds__(128) qkv_kernel(
    const float* __restrict__ emb,
    const float* __restrict__ wq,
    const float* __restrict__ wk,
    const float* __restrict__ wv,
    int n)
{
    __shared__ __align__(16) float et[DIM][20];   // 80B stride: 16B aligned, bank spread
    const int j  = threadIdx.x;                   // output column 0..127
    const int r0 = blockIdx.x * GR;

    #pragma unroll
    for (int r = 0; r < GR; r++) {
        int row = r0 + r;
        et[j][r] = (row < n) ? emb[row * DIM + j] : 0.f;
    }
    __syncthreads();

    unsigned long long aq[8], ak[8], av[8];
    #pragma unroll
    for (int i = 0; i < 8; i++) { aq[i] = 0ull; ak[i] = 0ull; av[i] = 0ull; }

    #pragma unroll 4
    for (int k = 0; k < DIM; k++) {
        unsigned long long q2 = bcast2(__ldg(&wq[k * DIM + j]));
        unsigned long long k2 = bcast2(__ldg(&wk[k * DIM + j]));
        unsigned long long v2 = bcast2(__ldg(&wv[k * DIM + j]));
        const ulonglong2* ep = (const ulonglong2*)(&et[k][0]);
        #pragma unroll
        for (int p = 0; p < 4; p++) {
            ulonglong2 e2 = ep[p];
            ffma2(aq[2 * p],     e2.x, q2);
            ffma2(aq[2 * p + 1], e2.y, q2);
            ffma2(ak[2 * p],     e2.x, k2);
            ffma2(ak[2 * p + 1], e2.y, k2);
            ffma2(av[2 * p],     e2.x, v2);
            ffma2(av[2 * p + 1], e2.y, v2);
        }
    }

    #pragma unroll
    for (int i = 0; i < 8; i++) {
        float qlo, qhi, klo, khi, vlo, vhi;
        unpack2(aq[i], qlo, qhi);
        unpack2(ak[i], klo, khi);
        unpack2(av[i], vlo, vhi);
        int row = r0 + 2 * i;
        if (row < n) {
            g_Q[row * DIM + j] = qlo;
            g_K[row * DIM + j] = klo;
            g_V[row * DIM + j] = vlo;
        }
        if (row + 1 < n) {
            g_Q[(row + 1) * DIM + j] = qhi;
            g_K[(row + 1) * DIM + j] = khi;
            g_V[(row + 1) * DIM + j] = vhi;
        }
    }
}

// ---------------- kernel 2: degree histogram ----------------
__global__ void hist_kernel(const int* __restrict__ rows, int E) {
    int i = blockIdx.x * blockDim.x + threadIdx.x;
    if (i < E) atomicAdd(&g_deg[rows[i]], 1);
}

// ---------------- scan phase 1: per-block sums (256 thr, 2048 elems/block) ----------------
__global__ void __launch_bounds__(256) scan_p1_kernel(int n) {
    __shared__ int ws[8];
    const int tid  = threadIdx.x;
    const int lane = tid & 31;
    const int wid  = tid >> 5;
    int base = blockIdx.x * SCAN_TILE + tid * 8;

    const int4* d4 = (const int4*)&g_deg[base];
    int s = 0;
    if (base < n) {
        int4 a = d4[0], b = d4[1];
        s = a.x + a.y + a.z + a.w + b.x + b.y + b.z + b.w;  // pad is zero
    }
    #pragma unroll
    for (int off = 16; off; off >>= 1) s += __shfl_xor_sync(0xffffffffu, s, off);
    if (lane == 0) ws[wid] = s;
    __syncthreads();
    if (tid == 0) {
        int t = 0;
        #pragma unroll
        for (int w = 0; w < 8; w++) t += ws[w];
        g_bsum[blockIdx.x] = t;
    }
}

// ---------------- scan phase 2: scan block sums (1 warp) ----------------
__global__ void scan_p2_kernel(int nblocks, int n) {
    int lane = threadIdx.x;
    // serial-ish exclusive scan across up to SCAN_MAXB in chunks of 32
    __shared__ int carry;
    if (lane == 0) carry = 0;
    __syncwarp();
    for (int b0 = 0; b0 < nblocks; b0 += 32) {
        int i = b0 + lane;
        int v = (i < nblocks) ? g_bsum[i] : 0;
        int inc = v;
        #pragma unroll
        for (int off = 1; off < 32; off <<= 1) {
            int t = __shfl_up_sync(0xffffffffu, inc, off);
            if (lane >= off) inc += t;
        }
        int c = carry;
        if (i < nblocks) g_boff[i] = c + inc - v;
        if (lane == 31) carry = c + inc;
        __syncwarp();
    }
    if (lane == 0) g_rowptr[n] = carry;   // grand total
}

// ---------------- scan phase 3: rescan tiles with offsets ----------------
__global__ void __launch_bounds__(256) scan_p3_kernel(int n) {
    __shared__ int warp_off[8];
    const int tid  = threadIdx.x;
    const int lane = tid & 31;
    const int wid  = tid >> 5;
    int base = blockIdx.x * SCAN_TILE + tid * 8;

    int v[8];
    int tot = 0;
    if (base < n) {
        const int4* d4 = (const int4*)&g_deg[base];
        int4 a = d4[0], b = d4[1];
        int d[8] = {a.x, a.y, a.z, a.w, b.x, b.y, b.z, b.w};
        #pragma unroll
        for (int i = 0; i < 8; i++) { v[i] = tot; tot += d[i]; }
    } else {
        #pragma unroll
        for (int i = 0; i < 8; i++) v[i] = 0;
    }

    int inc = tot;
    #pragma unroll
    for (int off = 1; off < 32; off <<= 1) {
        int t = __shfl_up_sync(0xffffffffu, inc, off);
        if (lane >= off) inc += t;
    }
    if (lane == 31) warp_off[wid] = inc;
    int texcl = inc - tot;
    __syncthreads();

    if (wid == 0 && lane < 8) {
        int w = warp_off[lane];
        int wi = w;
        #pragma unroll
        for (int off = 1; off < 8; off <<= 1) {
            int t = __shfl_up_sync(0x000000ffu, wi, off);
            if (lane >= off) wi += t;
        }
        warp_off[lane] = wi - w;
    }
    __syncthreads();

    int b = g_boff[blockIdx.x] + warp_off[wid] + texcl;
    #pragma unroll
    for (int i = 0; i < 8; i++) {
        int idx = base + i;
        if (idx < n) {
            int val = b + v[i];
            g_rowptr[idx] = val;
            g_cursor[idx] = val;
        }
    }
}

// ---------------- kernel 4: scatter edge ids into CSR ----------------
__global__ void scatter_kernel(const int* __restrict__ rows, int E) {
    int i = blockIdx.x * blockDim.x + threadIdx.x;
    if (i < E) {
        int pos = atomicAdd(&g_cursor[rows[i]], 1);
        g_eperm[pos] = i;
    }
}

// ---------------- kernel 5: fused segment-softmax attention ----------------
// One warp per destination node. Lane l holds dims [4l, 4l+4); head = l>>3.
__global__ void __launch_bounds__(256) attn_kernel(
    const int* __restrict__ cols, float* __restrict__ out, int n)
{
    int gw   = (blockIdx.x * blockDim.x + threadIdx.x) >> 5;
    int lane = threadIdx.x & 31;
    if (gw >= n) return;

    const float4* Q4 = (const float4*)g_Q;
    const float4* K4 = (const float4*)g_K;
    const float4* V4 = (const float4*)g_V;

    float4 qv = Q4[gw * 32 + lane];
    int beg = g_rowptr[gw];
    int end = g_rowptr[gw + 1];

    // pass A: logits -> exp -> stash, accumulate per-head norm
    float nsum = 0.f;
    for (int idx = beg; idx < end; idx++) {
        int e = g_eperm[idx];
        int c = __ldg(&cols[e]);
        float4 kv = K4[c * 32 + lane];
        float p = fmaf(qv.x, kv.x, fmaf(qv.y, kv.y, fmaf(qv.z, kv.z, qv.w * kv.w)));
        p += __shfl_xor_sync(0xffffffffu, p, 1);
        p += __shfl_xor_sync(0xffffffffu, p, 2);
        p += __shfl_xor_sync(0xffffffffu, p, 4);   // full head dot in all 8 lanes of group
        float a  = fminf(fmaxf(p, -10.f), 10.f);
        float ea = __expf(a);
        if ((lane & 7) == 0) g_expAtt[e * 4 + (lane >> 3)] = ea;
        nsum += ea;
    }
    __syncwarp();

    // pass B: normalize and accumulate V
    float inv = 1.f / (nsum + 1e-8f);
    int h = lane >> 3;
    float4 acc = make_float4(0.f, 0.f, 0.f, 0.f);
    for (int idx = beg; idx < end; idx++) {
        int e = g_eperm[idx];
        int c = __ldg(&cols[e]);
        float w = g_expAtt[e * 4 + h] * inv;
        float4 vv = V4[c * 32 + lane];
        acc.x = fmaf(w, vv.x, acc.x);
        acc.y = fmaf(w, vv.y, acc.y);
        acc.z = fmaf(w, vv.z, acc.z);
        acc.w = fmaf(w, vv.w, acc.w);
    }
    ((float4*)out)[gw * 32 + lane] = acc;
}

// ---------------- launch ----------------
extern "C" void kernel_launch(void* const* d_in, const int* in_sizes, int n_in,
                              void* d_out, int out_size) {
    const float* emb  = (const float*)d_in[0];
    const float* qW   = (const float*)d_in[1];
    const float* kW   = (const float*)d_in[2];
    const float* vW   = (const float*)d_in[3];
    const int*   rows = (const int*)d_in[4];
    const int*   cols = (const int*)d_in[5];
    float*       out  = (float*)d_out;

    const int N = in_sizes[0] / DIM;   // 50000
    const int E = in_sizes[4];         // 600000
    const int nsb = (N + SCAN_TILE - 1) / SCAN_TILE;   // 25

    zero_deg_kernel<<<(N + 8 + 255) / 256, 256>>>(N);
    qkv_kernel<<<(N + GR - 1) / GR, 128>>>(emb, qW, kW, vW, N);
    hist_kernel<<<(E + 255) / 256, 256>>>(rows, E);
    scan_p1_kernel<<<nsb, 256>>>(N);
    scan_p2_kernel<<<1, 32>>>(nsb, N);
    scan_p3_kernel<<<nsb, 256>>>(N);
    scatter_kernel<<<(E + 255) / 256, 256>>>(rows, E);
    attn_kernel<<<(N + 7) / 8, 256>>>(cols, out, N);
}

// round 9
// speedup vs baseline: 1.4899x; 1.0491x over previous
#include <cuda_runtime.h>
#include <cuda_bf16.h>

// Problem shape (fixed by dataset)
#define NMAX 50000
#define EMAX 600000
#define DIM  128
#define GR   32        // rows per block in QKV GEMM
#define SCAN_TILE 2048 // elems per scan block (256 thr x 8)
#define SCAN_MAXB 64   // max scan blocks (50000/2048 -> 25)

// ---------------- device scratch (static allocation only) ----------------
__device__ float g_Q[NMAX * DIM];
__device__ float g_K[NMAX * DIM];
__device__ float g_V[NMAX * DIM];
__device__ int   g_deg[NMAX + 8];      // padded so int4 loads never fault
__device__ int   g_rowptr[NMAX + 1];
__device__ int   g_cursor[NMAX];
__device__ int   g_ecol[EMAX];         // cols permuted into CSR order
__device__ int   g_bsum[SCAN_MAXB];
__device__ int   g_boff[SCAN_MAXB];

// ---------------- packed f32x2 helpers ----------------
__device__ __forceinline__ void ffma2(unsigned long long& acc,
                                      unsigned long long a,
                                      unsigned long long b) {
    asm("fma.rn.f32x2 %0, %1, %2, %0;" : "+l"(acc) : "l"(a), "l"(b));
}
__device__ __forceinline__ unsigned long long bcast2(float x) {
    unsigned long long r;
    unsigned u = __float_as_uint(x);
    asm("mov.b64 %0, {%1, %1};" : "=l"(r) : "r"(u));
    return r;
}
__device__ __forceinline__ void unpack2(unsigned long long v, float& lo, float& hi) {
    unsigned a, b;
    asm("mov.b64 {%0, %1}, %2;" : "=r"(a), "=r"(b) : "l"(v));
    lo = __uint_as_float(a);
    hi = __uint_as_float(b);
}

// ---------------- kernel 0: zero degree array (incl. pad) ----------------
__global__ void zero_deg_kernel(int n) {
    int i = blockIdx.x * blockDim.x + threadIdx.x;
    if (i < n + 8) g_deg[i] = 0;
}

// ---------------- kernel 1: fused Q/K/V projection (packed f32x2, GR=32) ----------------
// 128 threads = one output column j each; 32 rows per block.
// Shared tile k-major so adjacent rows pack into f32x2; fma.rn.f32x2 halves issue count.
__global__ void __launch_bounds__(128) qkv_kernel(
    const float* __restrict__ emb,
    const float* __restrict__ wq,
    const float* __restrict__ wk,
    const float* __restrict__ wv,
    int n)
{
    __shared__ __align__(16) float et[DIM][36];   // 144B stride: 16B aligned, bank spread
    const int j  = threadIdx.x;                   // output column 0..127
    const int r0 = blockIdx.x * GR;

    #pragma unroll
    for (int r = 0; r < GR; r++) {
        int row = r0 + r;
        et[j][r] = (row < n) ? emb[row * DIM + j] : 0.f;
    }
    __syncthreads();

    // 16 packed accumulators per matrix: pair i = rows (2i, 2i+1)
    unsigned long long aq[16], ak[16], av[16];
    #pragma unroll
    for (int i = 0; i < 16; i++) { aq[i] = 0ull; ak[i] = 0ull; av[i] = 0ull; }

    #pragma unroll 2
    for (int k = 0; k < DIM; k++) {
        unsigned long long q2 = bcast2(__ldg(&wq[k * DIM + j]));
        unsigned long long k2 = bcast2(__ldg(&wk[k * DIM + j]));
        unsigned long long v2 = bcast2(__ldg(&wv[k * DIM + j]));
        const ulonglong2* ep = (const ulonglong2*)(&et[k][0]);
        #pragma unroll
        for (int p = 0; p < 8; p++) {
            ulonglong2 e2 = ep[p];
            ffma2(aq[2 * p],     e2.x, q2);
            ffma2(aq[2 * p + 1], e2.y, q2);
            ffma2(ak[2 * p],     e2.x, k2);
            ffma2(ak[2 * p + 1], e2.y, k2);
            ffma2(av[2 * p],     e2.x, v2);
            ffma2(av[2 * p + 1], e2.y, v2);
        }
    }

    #pragma unroll
    for (int i = 0; i < 16; i++) {
        float qlo, qhi, klo, khi, vlo, vhi;
        unpack2(aq[i], qlo, qhi);
        unpack2(ak[i], klo, khi);
        unpack2(av[i], vlo, vhi);
        int row = r0 + 2 * i;
        if (row < n) {
            g_Q[row * DIM + j] = qlo;
            g_K[row * DIM + j] = klo;
            g_V[row * DIM + j] = vlo;
        }
        if (row + 1 < n) {
            g_Q[(row + 1) * DIM + j] = qhi;
            g_K[(row + 1) * DIM + j] = khi;
            g_V[(row + 1) * DIM + j] = vhi;
        }
    }
}

// ---------------- kernel 2: degree histogram ----------------
__global__ void hist_kernel(const int* __restrict__ rows, int E) {
    int i = blockIdx.x * blockDim.x + threadIdx.x;
    if (i < E) atomicAdd(&g_deg[rows[i]], 1);
}

// ---------------- scan phase 1: per-block sums ----------------
__global__ void __launch_bounds__(256) scan_p1_kernel(int n) {
    __shared__ int ws[8];
    const int tid  = threadIdx.x;
    const int lane = tid & 31;
    const int wid  = tid >> 5;
    int base = blockIdx.x * SCAN_TILE + tid * 8;

    const int4* d4 = (const int4*)&g_deg[base];
    int s = 0;
    if (base < n) {
        int4 a = d4[0], b = d4[1];
        s = a.x + a.y + a.z + a.w + b.x + b.y + b.z + b.w;  // pad is zero
    }
    #pragma unroll
    for (int off = 16; off; off >>= 1) s += __shfl_xor_sync(0xffffffffu, s, off);
    if (lane == 0) ws[wid] = s;
    __syncthreads();
    if (tid == 0) {
        int t = 0;
        #pragma unroll
        for (int w = 0; w < 8; w++) t += ws[w];
        g_bsum[blockIdx.x] = t;
    }
}

// ---------------- scan phase 2: scan block sums (1 warp) ----------------
__global__ void scan_p2_kernel(int nblocks, int n) {
    int lane = threadIdx.x;
    __shared__ int carry;
    if (lane == 0) carry = 0;
    __syncwarp();
    for (int b0 = 0; b0 < nblocks; b0 += 32) {
        int i = b0 + lane;
        int v = (i < nblocks) ? g_bsum[i] : 0;
        int inc = v;
        #pragma unroll
        for (int off = 1; off < 32; off <<= 1) {
            int t = __shfl_up_sync(0xffffffffu, inc, off);
            if (lane >= off) inc += t;
        }
        int c = carry;
        if (i < nblocks) g_boff[i] = c + inc - v;
        if (lane == 31) carry = c + inc;
        __syncwarp();
    }
    if (lane == 0) g_rowptr[n] = carry;   // grand total
}

// ---------------- scan phase 3: rescan tiles with offsets ----------------
__global__ void __launch_bounds__(256) scan_p3_kernel(int n) {
    __shared__ int warp_off[8];
    const int tid  = threadIdx.x;
    const int lane = tid & 31;
    const int wid  = tid >> 5;
    int base = blockIdx.x * SCAN_TILE + tid * 8;

    int v[8];
    int tot = 0;
    if (base < n) {
        const int4* d4 = (const int4*)&g_deg[base];
        int4 a = d4[0], b = d4[1];
        int d[8] = {a.x, a.y, a.z, a.w, b.x, b.y, b.z, b.w};
        #pragma unroll
        for (int i = 0; i < 8; i++) { v[i] = tot; tot += d[i]; }
    } else {
        #pragma unroll
        for (int i = 0; i < 8; i++) v[i] = 0;
    }

    int inc = tot;
    #pragma unroll
    for (int off = 1; off < 32; off <<= 1) {
        int t = __shfl_up_sync(0xffffffffu, inc, off);
        if (lane >= off) inc += t;
    }
    if (lane == 31) warp_off[wid] = inc;
    int texcl = inc - tot;
    __syncthreads();

    if (wid == 0 && lane < 8) {
        int w = warp_off[lane];
        int wi = w;
        #pragma unroll
        for (int off = 1; off < 8; off <<= 1) {
            int t = __shfl_up_sync(0x000000ffu, wi, off);
            if (lane >= off) wi += t;
        }
        warp_off[lane] = wi - w;
    }
    __syncthreads();

    int b = g_boff[blockIdx.x] + warp_off[wid] + texcl;
    #pragma unroll
    for (int i = 0; i < 8; i++) {
        int idx = base + i;
        if (idx < n) {
            int val = b + v[i];
            g_rowptr[idx] = val;
            g_cursor[idx] = val;
        }
    }
}

// ---------------- kernel 4: scatter col ids into CSR order ----------------
__global__ void scatter_kernel(const int* __restrict__ rows,
                               const int* __restrict__ cols, int E) {
    int i = blockIdx.x * blockDim.x + threadIdx.x;
    if (i < E) {
        int pos = atomicAdd(&g_cursor[rows[i]], 1);
        g_ecol[pos] = cols[i];
    }
}

// ---------------- kernel 5: fused single-pass segment-softmax attention ----------------
// One warp per destination node. Lane l holds dims [4l, 4l+4); head = l>>3.
// out = (sum_e ea_e * v_e) / (sum_e ea_e + 1e-8)  — norm factored out of the sum.
__global__ void __launch_bounds__(256) attn_kernel(float* __restrict__ out, int n)
{
    int gw   = (blockIdx.x * blockDim.x + threadIdx.x) >> 5;
    int lane = threadIdx.x & 31;
    if (gw >= n) return;

    const float4* Q4 = (const float4*)g_Q;
    const float4* K4 = (const float4*)g_K;
    const float4* V4 = (const float4*)g_V;

    float4 qv = Q4[gw * 32 + lane];
    int beg = g_rowptr[gw];
    int end = g_rowptr[gw + 1];

    float nsum = 0.f;
    float4 acc = make_float4(0.f, 0.f, 0.f, 0.f);
    for (int idx = beg; idx < end; idx++) {
        int c = g_ecol[idx];                      // sequential read, CSR order
        float4 kv = K4[c * 32 + lane];            // two independent row gathers:
        float4 vv = V4[c * 32 + lane];            // issue both before the dot
        float p = fmaf(qv.x, kv.x, fmaf(qv.y, kv.y, fmaf(qv.z, kv.z, qv.w * kv.w)));
        p += __shfl_xor_sync(0xffffffffu, p, 1);
        p += __shfl_xor_sync(0xffffffffu, p, 2);
        p += __shfl_xor_sync(0xffffffffu, p, 4);  // full head dot in all 8 lanes of group
        float a  = fminf(fmaxf(p, -10.f), 10.f);
        float ea = __expf(a);
        nsum += ea;
        acc.x = fmaf(ea, vv.x, acc.x);
        acc.y = fmaf(ea, vv.y, acc.y);
        acc.z = fmaf(ea, vv.z, acc.z);
        acc.w = fmaf(ea, vv.w, acc.w);
    }
    float inv = 1.f / (nsum + 1e-8f);
    acc.x *= inv; acc.y *= inv; acc.z *= inv; acc.w *= inv;
    ((float4*)out)[gw * 32 + lane] = acc;
}

// ---------------- launch ----------------
extern "C" void kernel_launch(void* const* d_in, const int* in_sizes, int n_in,
                              void* d_out, int out_size) {
    const float* emb  = (const float*)d_in[0];
    const float* qW   = (const float*)d_in[1];
    const float* kW   = (const float*)d_in[2];
    const float* vW   = (const float*)d_in[3];
    const int*   rows = (const int*)d_in[4];
    const int*   cols = (const int*)d_in[5];
    float*       out  = (float*)d_out;

    const int N = in_sizes[0] / DIM;   // 50000
    const int E = in_sizes[4];         // 600000
    const int nsb = (N + SCAN_TILE - 1) / SCAN_TILE;   // 25

    zero_deg_kernel<<<(N + 8 + 255) / 256, 256>>>(N);
    qkv_kernel<<<(N + GR - 1) / GR, 128>>>(emb, qW, kW, vW, N);
    hist_kernel<<<(E + 255) / 256, 256>>>(rows, E);
    scan_p1_kernel<<<nsb, 256>>>(N);
    scan_p2_kernel<<<1, 32>>>(nsb, N);
    scan_p3_kernel<<<nsb, 256>>>(N);
    scatter_kernel<<<(E + 255) / 256, 256>>>(rows, cols, E);
    attn_kernel<<<(N + 7) / 8, 256>>>(out, N);
}